// round 1
// baseline (speedup 1.0000x reference)
#include <cuda_runtime.h>

#define BATCH   1024
#define WDIM    256
#define HDIM    256
#define DEPTH   8
#define THREADS 256
#define NB      4      // batches per thread
#define WTILE   2      // w rows per CTA

// Persistent scratch: order-preserving uint keys of q per (branch, level, batch).
// Level 0 unused (q0 comes straight from val); levels 1..8 written by layer d -> d+1.
__device__ unsigned g_qkey[2][DEPTH + 1][BATCH];

// Monotone float -> uint mapping (uint order == float order), no NaNs in data.
__device__ __forceinline__ unsigned fkey(float f) {
    unsigned u = __float_as_uint(f);
    return (u & 0x80000000u) ? ~u : (u | 0x80000000u);
}
__device__ __forceinline__ float funkey(unsigned k) {
    unsigned u = (k & 0x80000000u) ? (k & 0x7FFFFFFFu) : ~k;
    return __uint_as_float(u);
}

__global__ void init_kernel() {
    int i = blockIdx.x * blockDim.x + threadIdx.x;
    // 2 * 9 * 1024 = 18432 entries; 0xFFFFFFFF == key(+NaN) > key(any finite float)
    ((unsigned*)g_qkey)[i] = 0xFFFFFFFFu;
}

// One layer step for both branches.
// grid: (WDIM/WTILE, BATCH/(THREADS*NB), 2), block: THREADS
__global__ void __launch_bounds__(THREADS, 4)
layer_kernel(const float* __restrict__ M1, const float* __restrict__ B1,
             const float* __restrict__ M2, const float* __restrict__ B2,
             const float* __restrict__ val, int d) {
    const int branch = blockIdx.z;
    const float* Mp = (branch ? M2 : M1) + (size_t)d * WDIM * HDIM + blockIdx.x * WTILE * HDIM;
    const float* Bp = (branch ? B2 : B1) + (size_t)d * WDIM * HDIM + blockIdx.x * WTILE * HDIM;

    const int b0 = blockIdx.y * (THREADS * NB) + threadIdx.x;

    float q[NB];
#pragma unroll
    for (int i = 0; i < NB; i++) {
        int bi = b0 + i * THREADS;
        q[i] = (d == 0) ? val[bi] : funkey(g_qkey[branch][d][bi]);
    }

    float vmin[NB];
#pragma unroll
    for (int i = 0; i < NB; i++) vmin[i] = 3.4e38f;

    for (int w = 0; w < WTILE; w++) {
        const float4* m4 = (const float4*)(Mp + w * HDIM);
        const float4* b4 = (const float4*)(Bp + w * HDIM);
        float vmax[NB];
#pragma unroll
        for (int i = 0; i < NB; i++) vmax[i] = -3.4e38f;

#pragma unroll 8
        for (int j = 0; j < HDIM / 4; j++) {
            // All threads load the same address -> single L1 sector, broadcast.
            float4 mm = __ldg(m4 + j);
            float4 bb = __ldg(b4 + j);
#pragma unroll
            for (int i = 0; i < NB; i++) {
                float s0 = fmaf(q[i], mm.x, bb.x);
                float s1 = fmaf(q[i], mm.y, bb.y);
                float s2 = fmaf(q[i], mm.z, bb.z);
                float s3 = fmaf(q[i], mm.w, bb.w);
                // tree max: short dependency chain on vmax
                vmax[i] = fmaxf(vmax[i], fmaxf(fmaxf(s0, s1), fmaxf(s2, s3)));
            }
        }
#pragma unroll
        for (int i = 0; i < NB; i++) vmin[i] = fminf(vmin[i], vmax[i]);
    }

#pragma unroll
    for (int i = 0; i < NB; i++) {
        int bi = b0 + i * THREADS;
        atomicMin(&g_qkey[branch][d + 1][bi], fkey(vmin[i]));
    }
}

__global__ void decode_kernel(float* __restrict__ out) {
    int b = blockIdx.x * blockDim.x + threadIdx.x;  // 0..1023
    out[b]         = funkey(g_qkey[0][DEPTH][b]);
    out[BATCH + b] = funkey(g_qkey[1][DEPTH][b]);
}

extern "C" void kernel_launch(void* const* d_in, const int* in_sizes, int n_in,
                              void* d_out, int out_size) {
    const float* val = (const float*)d_in[0];
    const float* M1  = (const float*)d_in[1];
    const float* B1  = (const float*)d_in[2];
    const float* M2  = (const float*)d_in[3];
    const float* B2  = (const float*)d_in[4];
    float* out = (float*)d_out;

    init_kernel<<<(2 * (DEPTH + 1) * BATCH) / 256, 256>>>();

    dim3 grid(WDIM / WTILE, BATCH / (THREADS * NB), 2);
    for (int d = 0; d < DEPTH; d++) {
        layer_kernel<<<grid, THREADS>>>(M1, B1, M2, B2, val, d);
    }

    decode_kernel<<<BATCH / 256, 256>>>(out);
}